// round 7
// baseline (speedup 1.0000x reference)
#include <cuda_runtime.h>
#include <cuda_fp16.h>

#define DIM 64
#define MAXN 100000
#define MAXE 1200000

#define SCAN_TPB 256
#define SCAN_ITEMS 16
#define SCAN_TILE (SCAN_TPB * SCAN_ITEMS)   // 4096

// ---------------------------------------------------------------------------
// Scratch (static device globals; zero-initialized at module load).
// Invariant: g_deg == 0 at kernel_launch entry (k_scan re-zeros after use).
// ---------------------------------------------------------------------------
__device__ int    g_deg[MAXN];
__device__ int    g_off[MAXN + 1];
__device__ int    g_rank[MAXE];
__device__ int    g_ssrc[MAXE];
__device__ __half g_xh[(size_t)MAXN * DIM];
__device__ float  g_h[(size_t)MAXN * DIM];
__device__ int    g_bsum[64];

// ---------------------------------------------------------------------------
// K1: fused x->fp16 conversion + destination-degree histogram.
// Blocks [0, cvtBlocks) convert 16 floats/thread; remaining blocks do the
// histogram at 8 edges/thread (atomic return = in-bucket rank -> g_rank).
// ---------------------------------------------------------------------------
__global__ void k_hist_cvt(const int* __restrict__ dst,
                           const float* __restrict__ x,
                           int nE, int nFloats, int n, int cvtBlocks) {
    if (blockIdx.x < cvtBlocks) {
        int t = blockIdx.x * blockDim.x + threadIdx.x;
        int base = t * 16;
        if (base + 16 <= nFloats) {
            const float4* px = reinterpret_cast<const float4*>(x + base);
            __half2 h[8];
            #pragma unroll
            for (int q = 0; q < 4; ++q) {
                float4 v = px[q];
                h[q * 2 + 0] = __float22half2_rn(make_float2(v.x, v.y));
                h[q * 2 + 1] = __float22half2_rn(make_float2(v.z, v.w));
            }
            uint4* po = reinterpret_cast<uint4*>(g_xh + base);
            po[0] = *reinterpret_cast<uint4*>(&h[0]);
            po[1] = *reinterpret_cast<uint4*>(&h[4]);
        } else {
            for (int i = base; i < nFloats; ++i)
                g_xh[i] = __float2half_rn(x[i]);
        }
        return;
    }

    int t = (blockIdx.x - cvtBlocks) * blockDim.x + threadIdx.x;
    if (t == 0) g_off[n] = nE;
    int i8 = t * 8;
    if (i8 + 8 <= nE) {
        int4 d0 = *reinterpret_cast<const int4*>(dst + i8);
        int4 d1 = *reinterpret_cast<const int4*>(dst + i8 + 4);
        int4 r0, r1;
        r0.x = atomicAdd(&g_deg[d0.x], 1);
        r0.y = atomicAdd(&g_deg[d0.y], 1);
        r0.z = atomicAdd(&g_deg[d0.z], 1);
        r0.w = atomicAdd(&g_deg[d0.w], 1);
        r1.x = atomicAdd(&g_deg[d1.x], 1);
        r1.y = atomicAdd(&g_deg[d1.y], 1);
        r1.z = atomicAdd(&g_deg[d1.z], 1);
        r1.w = atomicAdd(&g_deg[d1.w], 1);
        *reinterpret_cast<int4*>(g_rank + i8) = r0;
        *reinterpret_cast<int4*>(g_rank + i8 + 4) = r1;
    } else {
        for (int i = i8; i < nE; ++i)
            g_rank[i] = atomicAdd(&g_deg[dst[i]], 1);
    }
}

// ---------------------------------------------------------------------------
// K2a: per-tile reduction of g_deg -> g_bsum[tile].
// ---------------------------------------------------------------------------
__global__ __launch_bounds__(SCAN_TPB) void k_reduce(int n) {
    int base = blockIdx.x * SCAN_TILE + threadIdx.x * SCAN_ITEMS;
    unsigned s = 0;
    if (base + SCAN_ITEMS <= n) {
        const int4* p = reinterpret_cast<const int4*>(g_deg + base);
        #pragma unroll
        for (int q = 0; q < SCAN_ITEMS / 4; ++q) {
            int4 v = p[q];
            s += (unsigned)(v.x + v.y) + (unsigned)(v.z + v.w);
        }
    } else {
        for (int q = 0; q < SCAN_ITEMS; ++q)
            if (base + q < n) s += (unsigned)g_deg[base + q];
    }
    #pragma unroll
    for (int d = 16; d; d >>= 1) s += __shfl_down_sync(0xFFFFFFFFu, s, d);
    __shared__ unsigned ws[8];
    if ((threadIdx.x & 31) == 0) ws[threadIdx.x >> 5] = s;
    __syncthreads();
    if (threadIdx.x < 8) {
        unsigned v = ws[threadIdx.x];
        #pragma unroll
        for (int d = 4; d; d >>= 1) v += __shfl_down_sync(0xFFu, v, d);
        if (threadIdx.x == 0) g_bsum[blockIdx.x] = (int)v;
    }
}

// ---------------------------------------------------------------------------
// K2b: per-tile scan; base = sum of preceding tile sums (one warp-reduce).
// Writes g_off; re-zeros g_deg for the next launch.
// ---------------------------------------------------------------------------
__global__ __launch_bounds__(SCAN_TPB) void k_scan(int n) {
    __shared__ unsigned s_wsum[8];
    __shared__ unsigned s_base;

    int tid = threadIdx.x;
    int lane = tid & 31;
    int wid = tid >> 5;
    int bid = blockIdx.x;
    int base = bid * SCAN_TILE + tid * SCAN_ITEMS;

    if (wid == 0) {
        unsigned v = 0;
        if (lane < bid) v = (unsigned)g_bsum[lane];
        if (lane + 32 < bid) v += (unsigned)g_bsum[lane + 32];
        #pragma unroll
        for (int d = 16; d; d >>= 1) v += __shfl_down_sync(0xFFFFFFFFu, v, d);
        if (lane == 0) s_base = v;
    }

    int items[SCAN_ITEMS];
    bool full = (base + SCAN_ITEMS) <= n;
    if (full) {
        const int4* p = reinterpret_cast<const int4*>(g_deg + base);
        #pragma unroll
        for (int q = 0; q < SCAN_ITEMS / 4; ++q) {
            int4 v = p[q];
            items[q * 4 + 0] = v.x; items[q * 4 + 1] = v.y;
            items[q * 4 + 2] = v.z; items[q * 4 + 3] = v.w;
        }
        int4 z = make_int4(0, 0, 0, 0);
        int4* pz = reinterpret_cast<int4*>(g_deg + base);
        #pragma unroll
        for (int q = 0; q < SCAN_ITEMS / 4; ++q) pz[q] = z;
    } else {
        #pragma unroll
        for (int q = 0; q < SCAN_ITEMS; ++q) {
            items[q] = (base + q < n) ? g_deg[base + q] : 0;
            if (base + q < n) g_deg[base + q] = 0;
        }
    }

    unsigned tsum = 0;
    #pragma unroll
    for (int q = 0; q < SCAN_ITEMS; ++q) tsum += (unsigned)items[q];

    unsigned inc = tsum;
    #pragma unroll
    for (int d = 1; d < 32; d <<= 1) {
        unsigned u = __shfl_up_sync(0xFFFFFFFFu, inc, d);
        if (lane >= d) inc += u;
    }
    if (lane == 31) s_wsum[wid] = inc;
    __syncthreads();
    if (wid == 0 && lane < 8) {
        unsigned w = s_wsum[lane];
        #pragma unroll
        for (int d = 1; d < 8; d <<= 1) {
            unsigned u = __shfl_up_sync(0xFFu, w, d);
            if (lane >= d) w += u;
        }
        s_wsum[lane] = w;
    }
    __syncthreads();

    unsigned warp_excl = (wid > 0) ? s_wsum[wid - 1] : 0u;
    unsigned running = s_base + warp_excl + (inc - tsum);

    if (full) {
        int4* po = reinterpret_cast<int4*>(g_off + base);
        #pragma unroll
        for (int q = 0; q < SCAN_ITEMS / 4; ++q) {
            int4 o;
            o.x = (int)running; running += (unsigned)items[q * 4 + 0];
            o.y = (int)running; running += (unsigned)items[q * 4 + 1];
            o.z = (int)running; running += (unsigned)items[q * 4 + 2];
            o.w = (int)running; running += (unsigned)items[q * 4 + 3];
            po[q] = o;
        }
    } else {
        #pragma unroll
        for (int q = 0; q < SCAN_ITEMS; ++q) {
            if (base + q < n) g_off[base + q] = (int)running;
            running += (unsigned)items[q];
        }
    }
}

// ---------------------------------------------------------------------------
// K3: atomic-free bucket fill: pos = g_off[dst] + precomputed rank.
// 8 edges/thread for deeper MLP on the random g_off gathers.
// ---------------------------------------------------------------------------
__global__ void k_fill(const int* __restrict__ src,
                       const int* __restrict__ dst, int nE) {
    int t = blockIdx.x * blockDim.x + threadIdx.x;
    int i8 = t * 8;
    if (i8 + 8 <= nE) {
        int4 d0 = *reinterpret_cast<const int4*>(dst + i8);
        int4 d1 = *reinterpret_cast<const int4*>(dst + i8 + 4);
        int4 s0 = *reinterpret_cast<const int4*>(src + i8);
        int4 s1 = *reinterpret_cast<const int4*>(src + i8 + 4);
        int4 r0 = *reinterpret_cast<const int4*>(g_rank + i8);
        int4 r1 = *reinterpret_cast<const int4*>(g_rank + i8 + 4);
        int o0 = __ldg(&g_off[d0.x]);
        int o1 = __ldg(&g_off[d0.y]);
        int o2 = __ldg(&g_off[d0.z]);
        int o3 = __ldg(&g_off[d0.w]);
        int o4 = __ldg(&g_off[d1.x]);
        int o5 = __ldg(&g_off[d1.y]);
        int o6 = __ldg(&g_off[d1.z]);
        int o7 = __ldg(&g_off[d1.w]);
        g_ssrc[o0 + r0.x] = s0.x;
        g_ssrc[o1 + r0.y] = s0.y;
        g_ssrc[o2 + r0.z] = s0.z;
        g_ssrc[o3 + r0.w] = s0.w;
        g_ssrc[o4 + r1.x] = s1.x;
        g_ssrc[o5 + r1.y] = s1.y;
        g_ssrc[o6 + r1.z] = s1.z;
        g_ssrc[o7 + r1.w] = s1.w;
    } else {
        for (int i = i8; i < nE; ++i)
            g_ssrc[g_off[dst[i]] + g_rank[i]] = src[i];
    }
}

// ---------------------------------------------------------------------------
// K4: aggregation over fp16 rows. One 8-lane group per node; each lane owns
// 8 halves (16B) of the 128B row -> one L2 line per edge. 8 gathers in
// flight; fp32 accumulation.
// ---------------------------------------------------------------------------
__global__ __launch_bounds__(256) void k_agg(int n) {
    int node = (blockIdx.x * blockDim.x + threadIdx.x) >> 3;
    int l = threadIdx.x & 7;
    if (node >= n) return;

    int begin = g_off[node];
    int end   = g_off[node + 1];
    const float4* xh = reinterpret_cast<const float4*>(g_xh);  // 8 halves/elem

    float acc[8] = {0.f, 0.f, 0.f, 0.f, 0.f, 0.f, 0.f, 0.f};
    int i = begin;

    #pragma unroll 1
    for (; i + 8 <= end; i += 8) {
        float4 raw[8];
        #pragma unroll
        for (int q = 0; q < 8; ++q) {
            int e = __ldg(&g_ssrc[i + q]);
            raw[q] = xh[(size_t)e * 8 + l];
        }
        #pragma unroll
        for (int q = 0; q < 8; ++q) {
            const __half2* h2 = reinterpret_cast<const __half2*>(&raw[q]);
            #pragma unroll
            for (int p = 0; p < 4; ++p) {
                float2 f = __half22float2(h2[p]);
                acc[p * 2 + 0] += f.x;
                acc[p * 2 + 1] += f.y;
            }
        }
    }
    #pragma unroll 1
    for (; i < end; ++i) {
        int e = __ldg(&g_ssrc[i]);
        float4 raw = xh[(size_t)e * 8 + l];
        const __half2* h2 = reinterpret_cast<const __half2*>(&raw);
        #pragma unroll
        for (int p = 0; p < 4; ++p) {
            float2 f = __half22float2(h2[p]);
            acc[p * 2 + 0] += f.x;
            acc[p * 2 + 1] += f.y;
        }
    }

    float invd = 1.0f / fmaxf((float)(end - begin), 1.0f);
    float4 o0 = make_float4(acc[0] * invd, acc[1] * invd, acc[2] * invd, acc[3] * invd);
    float4 o1 = make_float4(acc[4] * invd, acc[5] * invd, acc[6] * invd, acc[7] * invd);
    float4* ph = reinterpret_cast<float4*>(g_h + (size_t)node * DIM + l * 8);
    ph[0] = o0;
    ph[1] = o1;
}

// ---------------------------------------------------------------------------
// K5: linear out = h @ W^T + b. 64x64 tile per 256-thread block, 4x4
// register tiles, float4 smem loads.
// ---------------------------------------------------------------------------
__global__ __launch_bounds__(256) void k_gemm(
    const float* __restrict__ W, const float* __restrict__ b,
    float* __restrict__ out, int nNodes) {
    __shared__ float sW[DIM][68];
    __shared__ float sh[DIM][68];
    int tid = threadIdx.x;

    for (int i = tid; i < DIM * DIM; i += 256) {
        int j = i >> 6;
        int k = i & 63;
        sW[k][j] = W[i];
    }

    int n0 = blockIdx.x * 64;
    #pragma unroll
    for (int r = 0; r < 16; ++r) {
        int flat = r * 256 + tid;
        int nl = flat >> 6;
        int k  = flat & 63;
        int n = n0 + nl;
        float v = 0.f;
        if (n < nNodes) v = g_h[(size_t)n * DIM + k];
        sh[k][nl] = v;
    }
    __syncthreads();

    int tx = tid & 15;
    int ty = tid >> 4;
    int jc  = tx * 4;
    int nl0 = ty * 4;

    float accum[4][4];
    float4 bb = *reinterpret_cast<const float4*>(b + jc);
    #pragma unroll
    for (int a = 0; a < 4; ++a) {
        accum[a][0] = bb.x; accum[a][1] = bb.y;
        accum[a][2] = bb.z; accum[a][3] = bb.w;
    }

    #pragma unroll
    for (int k = 0; k < DIM; ++k) {
        float4 hv = *reinterpret_cast<const float4*>(&sh[k][nl0]);
        float4 wv = *reinterpret_cast<const float4*>(&sW[k][jc]);
        float ha[4] = {hv.x, hv.y, hv.z, hv.w};
        float wa[4] = {wv.x, wv.y, wv.z, wv.w};
        #pragma unroll
        for (int a = 0; a < 4; ++a)
            #pragma unroll
            for (int c2 = 0; c2 < 4; ++c2)
                accum[a][c2] += ha[a] * wa[c2];
    }

    #pragma unroll
    for (int a = 0; a < 4; ++a) {
        int n = n0 + nl0 + a;
        if (n < nNodes) {
            float4 o = make_float4(accum[a][0], accum[a][1],
                                   accum[a][2], accum[a][3]);
            *reinterpret_cast<float4*>(out + (size_t)n * DIM + jc) = o;
        }
    }
}

// ---------------------------------------------------------------------------
// Launch. Inputs: x [N*64 f32], src [E i32], dst [E i32], W [64*64 f32],
// b [64 f32]. Output: [N*64 f32].
// ---------------------------------------------------------------------------
extern "C" void kernel_launch(void* const* d_in, const int* in_sizes, int n_in,
                              void* d_out, int out_size) {
    const float* x   = (const float*)d_in[0];
    const int*   src = (const int*)d_in[1];
    const int*   dst = (const int*)d_in[2];
    const float* W   = (const float*)d_in[3];
    const float* b   = (const float*)d_in[4];
    float* out = (float*)d_out;

    int nNodes = in_sizes[0] / DIM;
    int nEdges = in_sizes[1];
    int nFloats = in_sizes[0];

    int cvtBlocks  = ((nFloats + 15) / 16 + 255) / 256;
    int histBlocks = ((nEdges + 7) / 8 + 255) / 256;
    int e8Blocks   = histBlocks;
    int scanTiles  = (nNodes + SCAN_TILE - 1) / SCAN_TILE;

    k_hist_cvt<<<cvtBlocks + histBlocks, 256>>>(dst, x, nEdges, nFloats, nNodes, cvtBlocks);
    k_reduce<<<scanTiles, SCAN_TPB>>>(nNodes);
    k_scan<<<scanTiles, SCAN_TPB>>>(nNodes);
    k_fill<<<e8Blocks, 256>>>(src, dst, nEdges);
    k_agg<<<(nNodes * 8 + 255) / 256, 256>>>(nNodes);
    k_gemm<<<(nNodes + 63) / 64, 256>>>(W, b, out, nNodes);
}

// round 8
// speedup vs baseline: 1.0970x; 1.0970x over previous
#include <cuda_runtime.h>
#include <cuda_fp16.h>

#define DIM 64
#define MAXN 100000
#define MAXE 1200000

#define SCAN_TPB 256
#define SCAN_ITEMS 16
#define SCAN_TILE (SCAN_TPB * SCAN_ITEMS)   // 4096

// ---------------------------------------------------------------------------
// Scratch (static device globals; zero-initialized at module load).
// Invariant: g_deg == 0 at kernel_launch entry (k_scan re-zeros after use).
// g_y holds y = x @ W^T in fp16 (the linear commutes through the mean).
// ---------------------------------------------------------------------------
__device__ int    g_deg[MAXN];
__device__ int    g_off[MAXN + 1];
__device__ int    g_rank[MAXE];
__device__ int    g_ssrc[MAXE];
__device__ __half g_y[(size_t)MAXN * DIM];
__device__ int    g_bsum[64];

// ---------------------------------------------------------------------------
// K1: fused y = x @ W^T (fp16 out) + destination-degree histogram.
// Blocks [0, gemmBlocks): 64-node x 64-col GEMM tile -> g_y (fp16).
// Blocks [gemmBlocks, ...): histogram, 8 edges/thread; atomic return value
// is the edge's in-bucket rank -> g_rank (makes the fill pass atomic-free).
// ---------------------------------------------------------------------------
__global__ __launch_bounds__(256) void k_gemm_hist(
    const float* __restrict__ x, const float* __restrict__ W,
    const int* __restrict__ dst, int nE, int nNodes, int gemmBlocks) {

    if (blockIdx.x < gemmBlocks) {
        __shared__ float sW[DIM][68];
        __shared__ float sh[DIM][68];
        int tid = threadIdx.x;

        for (int i = tid; i < DIM * DIM; i += 256) {
            int j = i >> 6;
            int k = i & 63;
            sW[k][j] = W[i];   // transposed: sW[k][out col]
        }

        int n0 = blockIdx.x * 64;
        #pragma unroll
        for (int r = 0; r < 16; ++r) {
            int flat = r * 256 + tid;
            int nl = flat >> 6;
            int k  = flat & 63;
            int n = n0 + nl;
            sh[k][nl] = (n < nNodes) ? x[(size_t)n * DIM + k] : 0.f;
        }
        __syncthreads();

        int tx = tid & 15;
        int ty = tid >> 4;
        int jc  = tx * 4;
        int nl0 = ty * 4;

        float accum[4][4];
        #pragma unroll
        for (int a = 0; a < 4; ++a)
            #pragma unroll
            for (int c2 = 0; c2 < 4; ++c2)
                accum[a][c2] = 0.f;

        #pragma unroll
        for (int k = 0; k < DIM; ++k) {
            float4 hv = *reinterpret_cast<const float4*>(&sh[k][nl0]);
            float4 wv = *reinterpret_cast<const float4*>(&sW[k][jc]);
            float ha[4] = {hv.x, hv.y, hv.z, hv.w};
            float wa[4] = {wv.x, wv.y, wv.z, wv.w};
            #pragma unroll
            for (int a = 0; a < 4; ++a)
                #pragma unroll
                for (int c2 = 0; c2 < 4; ++c2)
                    accum[a][c2] += ha[a] * wa[c2];
        }

        #pragma unroll
        for (int a = 0; a < 4; ++a) {
            int n = n0 + nl0 + a;
            if (n < nNodes) {
                __half2 h0 = __float22half2_rn(make_float2(accum[a][0], accum[a][1]));
                __half2 h1 = __float22half2_rn(make_float2(accum[a][2], accum[a][3]));
                uint2 pk = make_uint2(*reinterpret_cast<unsigned*>(&h0),
                                      *reinterpret_cast<unsigned*>(&h1));
                *reinterpret_cast<uint2*>(g_y + (size_t)n * DIM + jc) = pk;
            }
        }
        return;
    }

    int t = (blockIdx.x - gemmBlocks) * blockDim.x + threadIdx.x;
    if (t == 0) g_off[nNodes] = nE;
    int i8 = t * 8;
    if (i8 + 8 <= nE) {
        int4 d0 = *reinterpret_cast<const int4*>(dst + i8);
        int4 d1 = *reinterpret_cast<const int4*>(dst + i8 + 4);
        int4 r0, r1;
        r0.x = atomicAdd(&g_deg[d0.x], 1);
        r0.y = atomicAdd(&g_deg[d0.y], 1);
        r0.z = atomicAdd(&g_deg[d0.z], 1);
        r0.w = atomicAdd(&g_deg[d0.w], 1);
        r1.x = atomicAdd(&g_deg[d1.x], 1);
        r1.y = atomicAdd(&g_deg[d1.y], 1);
        r1.z = atomicAdd(&g_deg[d1.z], 1);
        r1.w = atomicAdd(&g_deg[d1.w], 1);
        *reinterpret_cast<int4*>(g_rank + i8) = r0;
        *reinterpret_cast<int4*>(g_rank + i8 + 4) = r1;
    } else {
        for (int i = i8; i < nE; ++i)
            g_rank[i] = atomicAdd(&g_deg[dst[i]], 1);
    }
}

// ---------------------------------------------------------------------------
// K2a: per-tile reduction of g_deg -> g_bsum[tile].
// ---------------------------------------------------------------------------
__global__ __launch_bounds__(SCAN_TPB) void k_reduce(int n) {
    int base = blockIdx.x * SCAN_TILE + threadIdx.x * SCAN_ITEMS;
    unsigned s = 0;
    if (base + SCAN_ITEMS <= n) {
        const int4* p = reinterpret_cast<const int4*>(g_deg + base);
        #pragma unroll
        for (int q = 0; q < SCAN_ITEMS / 4; ++q) {
            int4 v = p[q];
            s += (unsigned)(v.x + v.y) + (unsigned)(v.z + v.w);
        }
    } else {
        for (int q = 0; q < SCAN_ITEMS; ++q)
            if (base + q < n) s += (unsigned)g_deg[base + q];
    }
    #pragma unroll
    for (int d = 16; d; d >>= 1) s += __shfl_down_sync(0xFFFFFFFFu, s, d);
    __shared__ unsigned ws[8];
    if ((threadIdx.x & 31) == 0) ws[threadIdx.x >> 5] = s;
    __syncthreads();
    if (threadIdx.x < 8) {
        unsigned v = ws[threadIdx.x];
        #pragma unroll
        for (int d = 4; d; d >>= 1) v += __shfl_down_sync(0xFFu, v, d);
        if (threadIdx.x == 0) g_bsum[blockIdx.x] = (int)v;
    }
}

// ---------------------------------------------------------------------------
// K2b: per-tile scan; base = sum of preceding tile sums (one warp-reduce).
// Writes g_off; re-zeros g_deg for the next launch.
// ---------------------------------------------------------------------------
__global__ __launch_bounds__(SCAN_TPB) void k_scan(int n) {
    __shared__ unsigned s_wsum[8];
    __shared__ unsigned s_base;

    int tid = threadIdx.x;
    int lane = tid & 31;
    int wid = tid >> 5;
    int bid = blockIdx.x;
    int base = bid * SCAN_TILE + tid * SCAN_ITEMS;

    if (wid == 0) {
        unsigned v = 0;
        if (lane < bid) v = (unsigned)g_bsum[lane];
        if (lane + 32 < bid) v += (unsigned)g_bsum[lane + 32];
        #pragma unroll
        for (int d = 16; d; d >>= 1) v += __shfl_down_sync(0xFFFFFFFFu, v, d);
        if (lane == 0) s_base = v;
    }

    int items[SCAN_ITEMS];
    bool full = (base + SCAN_ITEMS) <= n;
    if (full) {
        const int4* p = reinterpret_cast<const int4*>(g_deg + base);
        #pragma unroll
        for (int q = 0; q < SCAN_ITEMS / 4; ++q) {
            int4 v = p[q];
            items[q * 4 + 0] = v.x; items[q * 4 + 1] = v.y;
            items[q * 4 + 2] = v.z; items[q * 4 + 3] = v.w;
        }
        int4 z = make_int4(0, 0, 0, 0);
        int4* pz = reinterpret_cast<int4*>(g_deg + base);
        #pragma unroll
        for (int q = 0; q < SCAN_ITEMS / 4; ++q) pz[q] = z;
    } else {
        #pragma unroll
        for (int q = 0; q < SCAN_ITEMS; ++q) {
            items[q] = (base + q < n) ? g_deg[base + q] : 0;
            if (base + q < n) g_deg[base + q] = 0;
        }
    }

    unsigned tsum = 0;
    #pragma unroll
    for (int q = 0; q < SCAN_ITEMS; ++q) tsum += (unsigned)items[q];

    unsigned inc = tsum;
    #pragma unroll
    for (int d = 1; d < 32; d <<= 1) {
        unsigned u = __shfl_up_sync(0xFFFFFFFFu, inc, d);
        if (lane >= d) inc += u;
    }
    if (lane == 31) s_wsum[wid] = inc;
    __syncthreads();
    if (wid == 0 && lane < 8) {
        unsigned w = s_wsum[lane];
        #pragma unroll
        for (int d = 1; d < 8; d <<= 1) {
            unsigned u = __shfl_up_sync(0xFFu, w, d);
            if (lane >= d) w += u;
        }
        s_wsum[lane] = w;
    }
    __syncthreads();

    unsigned warp_excl = (wid > 0) ? s_wsum[wid - 1] : 0u;
    unsigned running = s_base + warp_excl + (inc - tsum);

    if (full) {
        int4* po = reinterpret_cast<int4*>(g_off + base);
        #pragma unroll
        for (int q = 0; q < SCAN_ITEMS / 4; ++q) {
            int4 o;
            o.x = (int)running; running += (unsigned)items[q * 4 + 0];
            o.y = (int)running; running += (unsigned)items[q * 4 + 1];
            o.z = (int)running; running += (unsigned)items[q * 4 + 2];
            o.w = (int)running; running += (unsigned)items[q * 4 + 3];
            po[q] = o;
        }
    } else {
        #pragma unroll
        for (int q = 0; q < SCAN_ITEMS; ++q) {
            if (base + q < n) g_off[base + q] = (int)running;
            running += (unsigned)items[q];
        }
    }
}

// ---------------------------------------------------------------------------
// K3: atomic-free bucket fill: pos = g_off[dst] + precomputed rank.
// ---------------------------------------------------------------------------
__global__ void k_fill(const int* __restrict__ src,
                       const int* __restrict__ dst, int nE) {
    int t = blockIdx.x * blockDim.x + threadIdx.x;
    int i8 = t * 8;
    if (i8 + 8 <= nE) {
        int4 d0 = *reinterpret_cast<const int4*>(dst + i8);
        int4 d1 = *reinterpret_cast<const int4*>(dst + i8 + 4);
        int4 s0 = *reinterpret_cast<const int4*>(src + i8);
        int4 s1 = *reinterpret_cast<const int4*>(src + i8 + 4);
        int4 r0 = *reinterpret_cast<const int4*>(g_rank + i8);
        int4 r1 = *reinterpret_cast<const int4*>(g_rank + i8 + 4);
        int o0 = __ldg(&g_off[d0.x]);
        int o1 = __ldg(&g_off[d0.y]);
        int o2 = __ldg(&g_off[d0.z]);
        int o3 = __ldg(&g_off[d0.w]);
        int o4 = __ldg(&g_off[d1.x]);
        int o5 = __ldg(&g_off[d1.y]);
        int o6 = __ldg(&g_off[d1.z]);
        int o7 = __ldg(&g_off[d1.w]);
        g_ssrc[o0 + r0.x] = s0.x;
        g_ssrc[o1 + r0.y] = s0.y;
        g_ssrc[o2 + r0.z] = s0.z;
        g_ssrc[o3 + r0.w] = s0.w;
        g_ssrc[o4 + r1.x] = s1.x;
        g_ssrc[o5 + r1.y] = s1.y;
        g_ssrc[o6 + r1.z] = s1.z;
        g_ssrc[o7 + r1.w] = s1.w;
    } else {
        for (int i = i8; i < nE; ++i)
            g_ssrc[g_off[dst[i]] + g_rank[i]] = src[i];
    }
}

// ---------------------------------------------------------------------------
// K4: terminal aggregation. One 8-lane group per node; each lane owns 8
// halves (16B) of the 128B fp16 y-row. Gathers one L2 line per edge, fp32
// accumulation, adds bias, writes the FINAL output (no g_h round trip).
// ---------------------------------------------------------------------------
__global__ __launch_bounds__(256) void k_agg(const float* __restrict__ bias,
                                             float* __restrict__ out, int n) {
    int node = (blockIdx.x * blockDim.x + threadIdx.x) >> 3;
    int l = threadIdx.x & 7;
    if (node >= n) return;

    int begin = g_off[node];
    int end   = g_off[node + 1];
    const float4* yv = reinterpret_cast<const float4*>(g_y);  // 8 halves/elem

    float acc[8] = {0.f, 0.f, 0.f, 0.f, 0.f, 0.f, 0.f, 0.f};
    int i = begin;

    #pragma unroll 1
    for (; i + 8 <= end; i += 8) {
        float4 raw[8];
        #pragma unroll
        for (int q = 0; q < 8; ++q) {
            int e = __ldg(&g_ssrc[i + q]);
            raw[q] = yv[(size_t)e * 8 + l];
        }
        #pragma unroll
        for (int q = 0; q < 8; ++q) {
            const __half2* h2 = reinterpret_cast<const __half2*>(&raw[q]);
            #pragma unroll
            for (int p = 0; p < 4; ++p) {
                float2 f = __half22float2(h2[p]);
                acc[p * 2 + 0] += f.x;
                acc[p * 2 + 1] += f.y;
            }
        }
    }
    #pragma unroll 1
    for (; i < end; ++i) {
        int e = __ldg(&g_ssrc[i]);
        float4 raw = yv[(size_t)e * 8 + l];
        const __half2* h2 = reinterpret_cast<const __half2*>(&raw);
        #pragma unroll
        for (int p = 0; p < 4; ++p) {
            float2 f = __half22float2(h2[p]);
            acc[p * 2 + 0] += f.x;
            acc[p * 2 + 1] += f.y;
        }
    }

    float invd = 1.0f / fmaxf((float)(end - begin), 1.0f);
    float4 b0 = *reinterpret_cast<const float4*>(bias + l * 8);
    float4 b1 = *reinterpret_cast<const float4*>(bias + l * 8 + 4);
    float4 o0 = make_float4(acc[0] * invd + b0.x, acc[1] * invd + b0.y,
                            acc[2] * invd + b0.z, acc[3] * invd + b0.w);
    float4 o1 = make_float4(acc[4] * invd + b1.x, acc[5] * invd + b1.y,
                            acc[6] * invd + b1.z, acc[7] * invd + b1.w);
    float4* po = reinterpret_cast<float4*>(out + (size_t)node * DIM + l * 8);
    po[0] = o0;
    po[1] = o1;
}

// ---------------------------------------------------------------------------
// Launch. Inputs: x [N*64 f32], src [E i32], dst [E i32], W [64*64 f32],
// b [64 f32]. Output: [N*64 f32].
// ---------------------------------------------------------------------------
extern "C" void kernel_launch(void* const* d_in, const int* in_sizes, int n_in,
                              void* d_out, int out_size) {
    const float* x   = (const float*)d_in[0];
    const int*   src = (const int*)d_in[1];
    const int*   dst = (const int*)d_in[2];
    const float* W   = (const float*)d_in[3];
    const float* b   = (const float*)d_in[4];
    float* out = (float*)d_out;

    int nNodes = in_sizes[0] / DIM;
    int nEdges = in_sizes[1];

    int gemmBlocks = (nNodes + 63) / 64;
    int histBlocks = ((nEdges + 7) / 8 + 255) / 256;
    int scanTiles  = (nNodes + SCAN_TILE - 1) / SCAN_TILE;

    k_gemm_hist<<<gemmBlocks + histBlocks, 256>>>(x, W, dst, nEdges, nNodes, gemmBlocks);
    k_reduce<<<scanTiles, SCAN_TPB>>>(nNodes);
    k_scan<<<scanTiles, SCAN_TPB>>>(nNodes);
    k_fill<<<histBlocks, 256>>>(src, dst, nEdges);
    k_agg<<<(nNodes * 8 + 255) / 256, 256>>>(b, out, nNodes);
}

// round 9
// speedup vs baseline: 1.1533x; 1.0514x over previous
#include <cuda_runtime.h>
#include <cuda_fp16.h>

#define DIM 64
#define MAXN 100000
#define MAXE 1200000

#define SCAN_TPB 256
#define SCAN_ITEMS 16
#define SCAN_TILE (SCAN_TPB * SCAN_ITEMS)   // 4096

// ---------------------------------------------------------------------------
// Scratch (static device globals; zero-initialized at module load).
// Invariant: g_deg == 0 at kernel_launch entry (scan re-zeros after use).
// g_y holds y = x @ W^T in fp16 (the linear commutes through the mean).
// g_bgen is a monotonically increasing barrier generation (never reset);
// g_bcnt self-resets each use.
// ---------------------------------------------------------------------------
__device__ int      g_deg[MAXN];
__device__ int      g_off[MAXN + 1];
__device__ int      g_rank[MAXE];
__device__ int      g_ssrc[MAXE];
__device__ __half   g_y[(size_t)MAXN * DIM];
__device__ int      g_bsum[64];
__device__ unsigned g_bcnt;
__device__ unsigned g_bgen;

// Software grid barrier (all nblk blocks must be co-resident).
__device__ __forceinline__ void grid_bar(int nblk) {
    __syncthreads();
    if (threadIdx.x == 0) {
        __threadfence();
        unsigned gen = atomicAdd(&g_bgen, 0u);
        unsigned a = atomicAdd(&g_bcnt, 1u);
        if (a == (unsigned)nblk - 1u) {
            g_bcnt = 0u;
            __threadfence();
            atomicAdd(&g_bgen, 1u);
        } else {
            while (atomicAdd(&g_bgen, 0u) == gen) { __nanosleep(64); }
        }
        __threadfence();
    }
    __syncthreads();
}

// ---------------------------------------------------------------------------
// K1: fused y = x @ W^T (fp16 out) + destination-degree histogram.
// Blocks [0, gemmBlocks): 64-node x 64-col GEMM tile -> g_y (fp16).
// Blocks [gemmBlocks, ...): histogram, 4 edges/thread; atomic return value
// is the edge's in-bucket rank -> g_rank (makes the fill pass atomic-free).
// ---------------------------------------------------------------------------
__global__ __launch_bounds__(256) void k_gemm_hist(
    const float* __restrict__ x, const float* __restrict__ W,
    const int* __restrict__ dst, int nE, int nNodes, int gemmBlocks) {

    if (blockIdx.x < gemmBlocks) {
        __shared__ float sW[DIM][68];
        __shared__ float sh[DIM][68];
        int tid = threadIdx.x;

        for (int i = tid; i < DIM * DIM; i += 256) {
            int j = i >> 6;
            int k = i & 63;
            sW[k][j] = W[i];   // transposed: sW[k][out col]
        }

        int n0 = blockIdx.x * 64;
        #pragma unroll
        for (int r = 0; r < 16; ++r) {
            int flat = r * 256 + tid;
            int nl = flat >> 6;
            int k  = flat & 63;
            int n = n0 + nl;
            sh[k][nl] = (n < nNodes) ? x[(size_t)n * DIM + k] : 0.f;
        }
        __syncthreads();

        int tx = tid & 15;
        int ty = tid >> 4;
        int jc  = tx * 4;
        int nl0 = ty * 4;

        float accum[4][4];
        #pragma unroll
        for (int a = 0; a < 4; ++a)
            #pragma unroll
            for (int c2 = 0; c2 < 4; ++c2)
                accum[a][c2] = 0.f;

        #pragma unroll
        for (int k = 0; k < DIM; ++k) {
            float4 hv = *reinterpret_cast<const float4*>(&sh[k][nl0]);
            float4 wv = *reinterpret_cast<const float4*>(&sW[k][jc]);
            float ha[4] = {hv.x, hv.y, hv.z, hv.w};
            float wa[4] = {wv.x, wv.y, wv.z, wv.w};
            #pragma unroll
            for (int a = 0; a < 4; ++a)
                #pragma unroll
                for (int c2 = 0; c2 < 4; ++c2)
                    accum[a][c2] += ha[a] * wa[c2];
        }

        #pragma unroll
        for (int a = 0; a < 4; ++a) {
            int n = n0 + nl0 + a;
            if (n < nNodes) {
                __half2 h0 = __float22half2_rn(make_float2(accum[a][0], accum[a][1]));
                __half2 h1 = __float22half2_rn(make_float2(accum[a][2], accum[a][3]));
                uint2 pk = make_uint2(*reinterpret_cast<unsigned*>(&h0),
                                      *reinterpret_cast<unsigned*>(&h1));
                *reinterpret_cast<uint2*>(g_y + (size_t)n * DIM + jc) = pk;
            }
        }
        return;
    }

    int t = (blockIdx.x - gemmBlocks) * blockDim.x + threadIdx.x;
    if (t == 0) g_off[nNodes] = nE;
    int i4 = t * 4;
    if (i4 + 4 <= nE) {
        int4 d = *reinterpret_cast<const int4*>(dst + i4);
        int4 r;
        r.x = atomicAdd(&g_deg[d.x], 1);
        r.y = atomicAdd(&g_deg[d.y], 1);
        r.z = atomicAdd(&g_deg[d.z], 1);
        r.w = atomicAdd(&g_deg[d.w], 1);
        *reinterpret_cast<int4*>(g_rank + i4) = r;
    } else {
        for (int i = i4; i < nE; ++i)
            g_rank[i] = atomicAdd(&g_deg[dst[i]], 1);
    }
}

// ---------------------------------------------------------------------------
// K2: fused reduce + exclusive scan of g_deg -> g_off in ONE kernel.
// Phase 1: each block scans its 4096-tile locally (items kept in registers),
// publishes its tile total, then all <=64 blocks cross a software barrier.
// Phase 2: each block adds the prefix of preceding tile totals and writes
// offsets; re-zeros g_deg for the next launch.
// ---------------------------------------------------------------------------
__global__ __launch_bounds__(SCAN_TPB) void k_scan_fused(int n, int nblk) {
    __shared__ unsigned s_wsum[8];
    __shared__ unsigned s_base;

    int tid = threadIdx.x;
    int lane = tid & 31;
    int wid = tid >> 5;
    int bid = blockIdx.x;
    int base = bid * SCAN_TILE + tid * SCAN_ITEMS;

    int items[SCAN_ITEMS];
    bool full = (base + SCAN_ITEMS) <= n;
    if (full) {
        const int4* p = reinterpret_cast<const int4*>(g_deg + base);
        #pragma unroll
        for (int q = 0; q < SCAN_ITEMS / 4; ++q) {
            int4 v = p[q];
            items[q * 4 + 0] = v.x; items[q * 4 + 1] = v.y;
            items[q * 4 + 2] = v.z; items[q * 4 + 3] = v.w;
        }
        int4 z = make_int4(0, 0, 0, 0);
        int4* pz = reinterpret_cast<int4*>(g_deg + base);
        #pragma unroll
        for (int q = 0; q < SCAN_ITEMS / 4; ++q) pz[q] = z;
    } else {
        #pragma unroll
        for (int q = 0; q < SCAN_ITEMS; ++q) {
            items[q] = (base + q < n) ? g_deg[base + q] : 0;
            if (base + q < n) g_deg[base + q] = 0;
        }
    }

    unsigned tsum = 0;
    #pragma unroll
    for (int q = 0; q < SCAN_ITEMS; ++q) tsum += (unsigned)items[q];

    unsigned inc = tsum;
    #pragma unroll
    for (int d = 1; d < 32; d <<= 1) {
        unsigned u = __shfl_up_sync(0xFFFFFFFFu, inc, d);
        if (lane >= d) inc += u;
    }
    if (lane == 31) s_wsum[wid] = inc;
    __syncthreads();
    if (wid == 0 && lane < 8) {
        unsigned w = s_wsum[lane];
        #pragma unroll
        for (int d = 1; d < 8; d <<= 1) {
            unsigned u = __shfl_up_sync(0xFFu, w, d);
            if (lane >= d) w += u;
        }
        s_wsum[lane] = w;
    }
    __syncthreads();

    unsigned warp_excl = (wid > 0) ? s_wsum[wid - 1] : 0u;
    unsigned block_total = s_wsum[7];
    unsigned thread_excl = warp_excl + (inc - tsum);

    if (tid == 0) g_bsum[bid] = (int)block_total;

    // ---- cross-tile barrier (<=64 blocks, trivially co-resident) ----
    grid_bar(nblk);

    // Prefix of preceding tile totals.
    if (wid == 0) {
        unsigned v = 0;
        if (lane < bid) v = (unsigned)g_bsum[lane];
        if (lane + 32 < bid) v += (unsigned)g_bsum[lane + 32];
        #pragma unroll
        for (int d = 16; d; d >>= 1) v += __shfl_down_sync(0xFFFFFFFFu, v, d);
        if (lane == 0) s_base = v;
    }
    __syncthreads();

    unsigned running = s_base + thread_excl;
    if (full) {
        int4* po = reinterpret_cast<int4*>(g_off + base);
        #pragma unroll
        for (int q = 0; q < SCAN_ITEMS / 4; ++q) {
            int4 o;
            o.x = (int)running; running += (unsigned)items[q * 4 + 0];
            o.y = (int)running; running += (unsigned)items[q * 4 + 1];
            o.z = (int)running; running += (unsigned)items[q * 4 + 2];
            o.w = (int)running; running += (unsigned)items[q * 4 + 3];
            po[q] = o;
        }
    } else {
        #pragma unroll
        for (int q = 0; q < SCAN_ITEMS; ++q) {
            if (base + q < n) g_off[base + q] = (int)running;
            running += (unsigned)items[q];
        }
    }
}

// ---------------------------------------------------------------------------
// K3: atomic-free bucket fill: pos = g_off[dst] + precomputed rank.
// 2 edges/thread -> 4x the blocks of round 8 for occupancy (was grid-limited
// at 35.8%); total outstanding L2 requests scale with resident threads.
// ---------------------------------------------------------------------------
__global__ __launch_bounds__(256) void k_fill(const int* __restrict__ src,
                                              const int* __restrict__ dst, int nE) {
    int t = blockIdx.x * blockDim.x + threadIdx.x;
    int i2 = t * 2;
    if (i2 + 2 <= nE) {
        int2 d = *reinterpret_cast<const int2*>(dst + i2);
        int2 s = *reinterpret_cast<const int2*>(src + i2);
        int2 r = *reinterpret_cast<const int2*>(g_rank + i2);
        int o0 = __ldg(&g_off[d.x]);
        int o1 = __ldg(&g_off[d.y]);
        g_ssrc[o0 + r.x] = s.x;
        g_ssrc[o1 + r.y] = s.y;
    } else {
        for (int i = i2; i < nE; ++i)
            g_ssrc[g_off[dst[i]] + g_rank[i]] = src[i];
    }
}

// ---------------------------------------------------------------------------
// K4: terminal aggregation. One 8-lane group per node; each lane owns 8
// halves (16B) of the 128B fp16 y-row. One L2 line per edge, fp32
// accumulation, adds bias, writes the FINAL output.
// ---------------------------------------------------------------------------
__global__ __launch_bounds__(256) void k_agg(const float* __restrict__ bias,
                                             float* __restrict__ out, int n) {
    int node = (blockIdx.x * blockDim.x + threadIdx.x) >> 3;
    int l = threadIdx.x & 7;
    if (node >= n) return;

    int begin = g_off[node];
    int end   = g_off[node + 1];
    const float4* yv = reinterpret_cast<const float4*>(g_y);  // 8 halves/elem

    float acc[8] = {0.f, 0.f, 0.f, 0.f, 0.f, 0.f, 0.f, 0.f};
    int i = begin;

    #pragma unroll 1
    for (; i + 8 <= end; i += 8) {
        float4 raw[8];
        #pragma unroll
        for (int q = 0; q < 8; ++q) {
            int e = __ldg(&g_ssrc[i + q]);
            raw[q] = yv[(size_t)e * 8 + l];
        }
        #pragma unroll
        for (int q = 0; q < 8; ++q) {
            const __half2* h2 = reinterpret_cast<const __half2*>(&raw[q]);
            #pragma unroll
            for (int p = 0; p < 4; ++p) {
                float2 f = __half22float2(h2[p]);
                acc[p * 2 + 0] += f.x;
                acc[p * 2 + 1] += f.y;
            }
        }
    }
    #pragma unroll 1
    for (; i < end; ++i) {
        int e = __ldg(&g_ssrc[i]);
        float4 raw = yv[(size_t)e * 8 + l];
        const __half2* h2 = reinterpret_cast<const __half2*>(&raw);
        #pragma unroll
        for (int p = 0; p < 4; ++p) {
            float2 f = __half22float2(h2[p]);
            acc[p * 2 + 0] += f.x;
            acc[p * 2 + 1] += f.y;
        }
    }

    float invd = 1.0f / fmaxf((float)(end - begin), 1.0f);
    float4 b0 = *reinterpret_cast<const float4*>(bias + l * 8);
    float4 b1 = *reinterpret_cast<const float4*>(bias + l * 8 + 4);
    float4 o0 = make_float4(acc[0] * invd + b0.x, acc[1] * invd + b0.y,
                            acc[2] * invd + b0.z, acc[3] * invd + b0.w);
    float4 o1 = make_float4(acc[4] * invd + b1.x, acc[5] * invd + b1.y,
                            acc[6] * invd + b1.z, acc[7] * invd + b1.w);
    float4* po = reinterpret_cast<float4*>(out + (size_t)node * DIM + l * 8);
    po[0] = o0;
    po[1] = o1;
}

// ---------------------------------------------------------------------------
// Launch. Inputs: x [N*64 f32], src [E i32], dst [E i32], W [64*64 f32],
// b [64 f32]. Output: [N*64 f32].
// ---------------------------------------------------------------------------
extern "C" void kernel_launch(void* const* d_in, const int* in_sizes, int n_in,
                              void* d_out, int out_size) {
    const float* x   = (const float*)d_in[0];
    const int*   src = (const int*)d_in[1];
    const int*   dst = (const int*)d_in[2];
    const float* W   = (const float*)d_in[3];
    const float* b   = (const float*)d_in[4];
    float* out = (float*)d_out;

    int nNodes = in_sizes[0] / DIM;
    int nEdges = in_sizes[1];

    int gemmBlocks = (nNodes + 63) / 64;
    int histBlocks = ((nEdges + 3) / 4 + 255) / 256;
    int fillBlocks = ((nEdges + 1) / 2 + 255) / 256;
    int scanTiles  = (nNodes + SCAN_TILE - 1) / SCAN_TILE;   // 25 for 100k

    k_gemm_hist<<<gemmBlocks + histBlocks, 256>>>(x, W, dst, nEdges, nNodes, gemmBlocks);
    k_scan_fused<<<scanTiles, SCAN_TPB>>>(nNodes, scanTiles);
    k_fill<<<fillBlocks, 256>>>(src, dst, nEdges);
    k_agg<<<(nNodes * 8 + 255) / 256, 256>>>(b, out, nNodes);
}